// round 12
// baseline (speedup 1.0000x reference)
#include <cuda_runtime.h>
#include <cstdint>

// ---------------------------------------------------------------------------
// Problem constants
// ---------------------------------------------------------------------------
#define NDET   128
#define HWPIX  661504            // 608 * 1088
#define NCHUNK (HWPIX / 128)     // 5168 K-chunks of 128 pixels
#define GRAMN  (NDET * NDET)
#define GRID   148

#define MASK_SCORE_THRESH 0.5f
#define MIN_MASK_PIXELS   20.0f
#define IOMIN_THRESH      0.9f
#define IOMAX_THRESH      0.5f
#define HIGH_SCORE_THRESH 0.5f
#define VIS_THRESH        0.1f
#define PED_LABEL         1

// s8 tile row pitch (128 data + 16 pad -> conflict-free ldmatrix)
#define TPITCH 144
#define TILE_BYTES (NDET * TPITCH)      // 18432

// fp32 stage: 128 rows x 512 B, double buffered
#define STAGE_BYTES (NDET * 512)        // 65536
#define NSTAGE 2
#define SMEM_DYN (NSTAGE * STAGE_BYTES + 2 * TILE_BYTES)   // 167936

// Global scratch. d_igram upper triangle valid; both re-zeroed by the last
// CTA of each run (statically zero for the very first call).
__device__ int d_igram[GRAMN];
__device__ int d_done;

// ---------------------------------------------------------------------------
// PTX helpers (sm_80+ portable; PTX target is plain sm_100)
// ---------------------------------------------------------------------------
__device__ __forceinline__ uint32_t smem_u32(const void* p) {
    uint32_t a;
    asm("{ .reg .u64 t; cvta.to.shared.u64 t, %1; cvt.u32.u64 %0, t; }"
        : "=r"(a) : "l"(p));
    return a;
}

#define CP_ASYNC16(dst, src)                                               \
    asm volatile("cp.async.cg.shared.global [%0], [%1], 16;"               \
                 :: "r"(dst), "l"(src) : "memory")
#define CP_COMMIT() asm volatile("cp.async.commit_group;" ::: "memory")
#define CP_WAIT1()  asm volatile("cp.async.wait_group 1;" ::: "memory")

#define LDSM_X4(r0, r1, r2, r3, addr)                                      \
    asm volatile("ldmatrix.sync.aligned.m8n8.x4.shared.b16 "               \
                 "{%0,%1,%2,%3}, [%4];"                                    \
                 : "=r"(r0), "=r"(r1), "=r"(r2), "=r"(r3) : "r"(addr))

#define IMMA16832(c, a0, a1, a2, a3, b0, b1)                               \
    asm volatile("mma.sync.aligned.m16n8k32.row.col.s32.s8.s8.s32 "        \
                 "{%0,%1,%2,%3}, {%4,%5,%6,%7}, {%8,%9}, {%0,%1,%2,%3};"   \
                 : "+r"((c)[0]), "+r"((c)[1]), "+r"((c)[2]), "+r"((c)[3])  \
                 : "r"(a0), "r"(a1), "r"(a2), "r"(a3), "r"(b0), "r"(b1))

__device__ __forceinline__ uint32_t setgt(float v) {
    uint32_t s;
    asm("set.gt.u32.f32 %0, %1, %2;" : "=r"(s) : "f"(v), "f"(MASK_SCORE_THRESH));
    return s;
}

// ---------------------------------------------------------------------------
// One 32x32 tile job (trow,tcol), ksteps [s_lo,s_hi). diag skips the 2
// below-diagonal micro-tiles.
// ---------------------------------------------------------------------------
__device__ __forceinline__ void mma_job(int acc[2][4][4], uint32_t tbase,
                                        int trow, int tcol, int s_lo, int s_hi,
                                        bool diag, uint32_t lrow, uint32_t lhalf) {
    const uint32_t abase = tbase + (uint32_t)(trow * 32 + (int)lrow) * TPITCH;
    const uint32_t bbase = tbase + (uint32_t)(tcol * 32 + (int)lrow) * TPITCH;
    for (int s = s_lo; s < s_hi; s++) {
        const uint32_t kb = (uint32_t)(32 * s) + lhalf;
        uint32_t a0, a1, a2, a3, a4, a5, a6, a7;
        LDSM_X4(a0, a1, a2, a3, abase + kb);
        LDSM_X4(a4, a5, a6, a7, abase + 16u * TPITCH + kb);
        uint32_t b0, b1, b2, b3, b4, b5, b6, b7;
        LDSM_X4(b0, b1, b2, b3, bbase + kb);
        LDSM_X4(b4, b5, b6, b7, bbase + 16u * TPITCH + kb);

        IMMA16832(acc[0][0], a0, a1, a2, a3, b0, b2);
        IMMA16832(acc[0][1], a0, a1, a2, a3, b1, b3);
        IMMA16832(acc[0][2], a0, a1, a2, a3, b4, b6);
        IMMA16832(acc[0][3], a0, a1, a2, a3, b5, b7);
        if (!diag) {
            IMMA16832(acc[1][0], a4, a5, a6, a7, b0, b2);
            IMMA16832(acc[1][1], a4, a5, a6, a7, b1, b3);
        }
        IMMA16832(acc[1][2], a4, a5, a6, a7, b4, b6);
        IMMA16832(acc[1][3], a4, a5, a6, a7, b5, b7);
    }
}

__device__ __forceinline__ void store_job(int acc[2][4][4], int trow, int tcol,
                                          bool diag, int l) {
    const int g4 = l >> 2;
    const int i2 = (l & 3) * 2;
#pragma unroll
    for (int mi = 0; mi < 2; mi++) {
#pragma unroll
        for (int g = 0; g < 4; g++) {
            if (diag && mi == 1 && g < 2) continue;
            int row = trow * 32 + 16 * mi + g4;
            int col = tcol * 32 + 8 * g + i2;
            atomicAdd(&d_igram[row * NDET + col],           acc[mi][g][0]);
            atomicAdd(&d_igram[row * NDET + col + 1],       acc[mi][g][1]);
            atomicAdd(&d_igram[(row + 8) * NDET + col],     acc[mi][g][2]);
            atomicAdd(&d_igram[(row + 8) * NDET + col + 1], acc[mi][g][3]);
        }
    }
}

// ---------------------------------------------------------------------------
// Single fused kernel:
//  Phase 1 (all 148 CTAs): warp-specialized binarize + upper-tri Gram with a
//  SINGLE __syncthreads per chunk.
//  Protocol: at rendezvous R(k), consumers have finished MMA(k-1) on
//  tile[b^1] (they arrive at R(k) only after it), so in interval k producers
//  binarize tile[b^1]... concretely:
//    producer: CP_WAIT -> binarize stage[b]->tile[b] -> SYNC -> refill[b]
//    consumer: SYNC -> MMA tile[b]
//  Tile disjointness: while consumers MMA tile[b], producers binarize
//  tile[b^1] (last consumed at MMA(k-1), finished before R(k)). bar.sync
//  drains STS natively -> no membar needed.
//  Phase 2 (last CTA): O(N^2) NMS / visibility finish + scratch re-zero.
// ---------------------------------------------------------------------------
__global__ void __launch_bounds__(512, 1)
postfilter_kernel(const float* __restrict__ masks,
                  const float* __restrict__ boxes,
                  const float* __restrict__ scores,
                  const int*   __restrict__ labels,
                  float*       __restrict__ out) {
    extern __shared__ __align__(16) char smem[];
    char* tiles = smem + NSTAGE * STAGE_BYTES;

    const int tid = threadIdx.x;
    const int w   = tid >> 5;
    const int l   = tid & 31;
    const int k0  = blockIdx.x;

    if (w < 8) {
        // ================= PRODUCER (warps 0-7) =================
        const int p = w;                       // rows 16p..16p+15
        const char* gbase = (const char*)masks +
                            (size_t)(16 * p) * HWPIX * 4 + (size_t)(16 * l);
        const uint32_t smem_base = smem_u32(smem);
        const uint32_t srow = (uint32_t)(16 * p) * 512u + (uint32_t)(16 * l);

        // prologue: fill both stages
#pragma unroll
        for (int s = 0; s < NSTAGE; s++) {
            int kk = k0 + s * GRID;
            if (kk < NCHUNK) {
                const char* g = gbase + (size_t)kk * 512;
                uint32_t d = smem_base + (uint32_t)s * STAGE_BYTES + srow;
#pragma unroll
                for (int r = 0; r < 16; r++)
                    CP_ASYNC16(d + (uint32_t)r * 512u, g + (size_t)r * HWPIX * 4);
            }
            CP_COMMIT();
        }

        int b = 0;
        for (int k = k0; k < NCHUNK; k += GRID, b ^= 1) {
            CP_WAIT1();              // stage[b] complete (this thread's bytes)

            // binarize stage[b] -> tile[b] (consumers are on tile[b^1])
            const float4* st = (const float4*)(smem + b * STAGE_BYTES);
            char* tb = tiles + b * TILE_BYTES;
#pragma unroll
            for (int r = 0; r < 16; r++) {
                float4 v = st[(16 * p + r) * 32 + l];
                uint32_t s0 = setgt(v.x), s1 = setgt(v.y);
                uint32_t s2 = setgt(v.z), s3 = setgt(v.w);
                uint32_t t0 = __byte_perm(s0, s1, 0x0040);
                uint32_t t1 = __byte_perm(s2, s3, 0x0040);
                uint32_t pk = __byte_perm(t0, t1, 0x5410) & 0x01010101u;
                *(uint32_t*)(tb + (uint32_t)(16 * p + r) * TPITCH + 4u * l) = pk;
            }

            __syncthreads();         // R(k): tile[b] published, STS drained

            // refill stage[b] with chunk k + 2*GRID (covered by MMA(k))
            int kn = k + NSTAGE * GRID;
            if (kn < NCHUNK) {
                const char* g = gbase + (size_t)kn * 512;
                uint32_t d = smem_base + (uint32_t)b * STAGE_BYTES + srow;
#pragma unroll
                for (int r = 0; r < 16; r++)
                    CP_ASYNC16(d + (uint32_t)r * 512u, g + (size_t)r * HWPIX * 4);
            }
            CP_COMMIT();
        }
    } else {
        // ================= CONSUMER (warps 8-15) =================
        const int cw = w - 8;
        const uint32_t lrow  = (uint32_t)(l & 15);
        const uint32_t lhalf = (uint32_t)((l >> 4) * 16);

        // job tables (two 32x32-tile jobs per warp, <=40 IMMA/chunk)
        static const int J0R[8]  = {0, 1, 2, 3, 0, 0, 0, 1};
        static const int J0C[8]  = {0, 1, 2, 3, 1, 2, 3, 2};
        static const int J0LO[8] = {0, 0, 0, 0, 2, 2, 2, 2};
        static const int J1R[8]  = {0, 0, 0, 1, 1, 1, 2, 2};
        static const int J1C[8]  = {1, 2, 3, 2, 3, 3, 3, 3};
        static const int J1LO[8] = {0, 0, 0, 0, 0, 2, 0, 2};
        static const int J1HI[8] = {2, 2, 2, 2, 2, 4, 2, 4};

        const int  t0r = J0R[cw], t0c = J0C[cw], s0lo = J0LO[cw];
        const int  s0hi = 4;
        const bool d0  = (cw < 4);
        const int  t1r = J1R[cw], t1c = J1C[cw], s1lo = J1LO[cw], s1hi = J1HI[cw];

        int accA[2][4][4], accB[2][4][4];
#pragma unroll
        for (int mi = 0; mi < 2; mi++)
#pragma unroll
            for (int g = 0; g < 4; g++)
#pragma unroll
                for (int e = 0; e < 4; e++) { accA[mi][g][e] = 0; accB[mi][g][e] = 0; }

        int b = 0;
        for (int k = k0; k < NCHUNK; k += GRID, b ^= 1) {
            __syncthreads();         // R(k): tile[b] ready
            const uint32_t tbase = smem_u32(tiles + b * TILE_BYTES);
            mma_job(accA, tbase, t0r, t0c, s0lo, s0hi, d0, lrow, lhalf);
            mma_job(accB, tbase, t1r, t1c, s1lo, s1hi, false, lrow, lhalf);
        }

        store_job(accA, t0r, t0c, d0, l);
        store_job(accB, t1r, t1c, false, l);
    }

    // ===================== last-CTA finish phase =====================
    __shared__ int s_rank;
    __syncthreads();
    if (tid == 0) {
        __threadfence();
        s_rank = atomicAdd(&d_done, 1);
    }
    __syncthreads();
    if (s_rank != GRID - 1) return;

    // --- O(N^2) finish, run by the last CTA (512 threads; j-work on tid<128)
    __shared__ float areas[NDET], ssc[NDET];
    __shared__ float x1s[NDET], y1s[NDET], x2s[NDET], y2s[NDET], bareas[NDET];
    __shared__ unsigned char confl[NDET * NDET];
    __shared__ int  ord[NDET];
    __shared__ unsigned char ks[NDET];
    __shared__ unsigned char keepO[NDET];

    const int j = tid;   // valid for tid < 128

    if (j < NDET) {
        areas[j] = (float)__ldcg(&d_igram[j * NDET + j]);
        ssc[j]   = scores[j];
        x1s[j] = boxes[j * 4 + 0];
        y1s[j] = boxes[j * 4 + 1];
        x2s[j] = boxes[j * 4 + 2];
        y2s[j] = boxes[j * 4 + 3];
    }
    __syncthreads();

    // conflict matrix: 512 threads, thread t -> row jj = t&127, i-slice t>>7
    {
        int jj = tid & 127;
        int i0 = (tid >> 7) * 32;
        float aj = areas[jj];
        for (int i = i0; i < i0 + 32; i++) {
            int lo = (i < jj) ? i : jj;
            int hi = (i < jj) ? jj : i;
            float inter = (float)__ldcg(&d_igram[lo * NDET + hi]);
            float ai    = areas[i];
            float amin  = fminf(ai, aj), amax = fmaxf(ai, aj);
            float iomin = inter / fmaxf(amin, 1.0f);
            float iomax = inter / fmaxf(amax, 1.0f);
            confl[jj * NDET + i] =
                ((iomin > IOMIN_THRESH) || (iomax > IOMAX_THRESH)) ? 1 : 0;
        }
    }
    __syncthreads();

    // re-zero scratch for the next replay (no more d_igram reads below)
    {
#pragma unroll
        for (int i = 0; i < GRAMN / 512; i++)
            d_igram[tid + 512 * i] = 0;
        if (tid == 0) d_done = 0;
    }

    // stable descending rank
    if (j < NDET) {
        const float sj = ssc[j];
        int r = 0;
        for (int i = 0; i < NDET; i++) {
            float si = ssc[i];
            r += (si > sj) || (si == sj && i < j);
        }
        ord[r] = j;
        ks[r]  = (areas[j] > MIN_MASK_PIXELS) ? 1 : 0;
    }
    __syncthreads();

    // greedy suppression (serial over i, parallel over j; all threads sync)
    for (int i = 0; i < NDET; i++) {
        if (j < NDET && j > i) {
            if (ks[i] && confl[ord[i] * NDET + ord[j]]) ks[j] = 0;
        }
        __syncthreads();
    }

    if (j < NDET) keepO[ord[j]] = ks[j];
    __syncthreads();
    if (j < NDET) {
        unsigned char kj = (keepO[j] && (labels[j] == PED_LABEL)) ? 1 : 0;
        __syncwarp();
        keepO[j] = kj;
        float wbx = x2s[j] - x1s[j], hbx = y2s[j] - y1s[j];
        bareas[j] = fmaxf(wbx * hbx, 1e-6f);
    }
    __syncthreads();

    if (j < NDET) {
        const float sj = ssc[j];
        const bool high_j = (sj >= HIGH_SCORE_THRESH);
        float cover = 0.0f;
        const float bj = bareas[j];
        for (int i = 0; i < NDET; i++) {
            bool occ = (ssc[i] >= HIGH_SCORE_THRESH) && keepO[i] && (i != j);
            if (occ) {
                float ix1 = fmaxf(x1s[i], x1s[j]);
                float iy1 = fmaxf(y1s[i], y1s[j]);
                float ix2 = fminf(x2s[i], x2s[j]);
                float iy2 = fminf(y2s[i], y2s[j]);
                float bi  = fmaxf(ix2 - ix1, 0.0f) * fmaxf(iy2 - iy1, 0.0f);
                cover = fmaxf(cover, bi / bj);
            }
        }
        float vis = 1.0f - cover;
        bool finalk = keepO[j] && (high_j || (vis < VIS_THRESH));
        out[j] = sj * (finalk ? 1.0f : 0.0f);
    }
}

// ---------------------------------------------------------------------------
// kernel_launch — inputs: boxes f32[128,4], scores f32[128], labels i32[128],
// masks f32[128,1,608,1088]; output f32[128].
// ---------------------------------------------------------------------------
extern "C" void kernel_launch(void* const* d_in, const int* in_sizes, int n_in,
                              void* d_out, int out_size) {
    const float* boxes  = (const float*)d_in[0];
    const float* scores = (const float*)d_in[1];
    const int*   labels = (const int*)d_in[2];
    const float* masks  = (const float*)d_in[3];
    float* out = (float*)d_out;

    static bool attr_set = false;
    if (!attr_set) {
        cudaFuncSetAttribute(postfilter_kernel,
                             cudaFuncAttributeMaxDynamicSharedMemorySize,
                             SMEM_DYN);
        attr_set = true;
    }

    postfilter_kernel<<<GRID, 512, SMEM_DYN>>>(masks, boxes, scores, labels, out);
}

// round 14
// speedup vs baseline: 1.0227x; 1.0227x over previous
#include <cuda_runtime.h>
#include <cstdint>

// ---------------------------------------------------------------------------
// Problem constants
// ---------------------------------------------------------------------------
#define NDET   128
#define HWPIX  661504            // 608 * 1088
#define NCHUNK (HWPIX / 128)     // 5168 K-chunks of 128 pixels
#define GRAMN  (NDET * NDET)
#define GRID   148
#define NTHREADS 1024

#define MASK_SCORE_THRESH 0.5f
#define MIN_MASK_PIXELS   20.0f
#define IOMIN_THRESH      0.9f
#define IOMAX_THRESH      0.5f
#define HIGH_SCORE_THRESH 0.5f
#define VIS_THRESH        0.1f
#define PED_LABEL         1

// s8 tile row pitch (128 data + 16 pad -> conflict-free ldmatrix)
#define TPITCH 144
#define TILE_BYTES (NDET * TPITCH)      // 18432

// fp32 stage: 128 rows x 512 B, double buffered
#define STAGE_BYTES (NDET * 512)        // 65536
#define NSTAGE 2
#define SMEM_DYN (NSTAGE * STAGE_BYTES + 2 * TILE_BYTES)   // 167936

// Global scratch. d_igram upper triangle valid; both re-zeroed by the last
// CTA of each run (statically zero for the very first call).
__device__ int d_igram[GRAMN];
__device__ int d_done;

// ---------------------------------------------------------------------------
// PTX helpers (sm_80+ portable; PTX target is plain sm_100)
// ---------------------------------------------------------------------------
__device__ __forceinline__ uint32_t smem_u32(const void* p) {
    uint32_t a;
    asm("{ .reg .u64 t; cvta.to.shared.u64 t, %1; cvt.u32.u64 %0, t; }"
        : "=r"(a) : "l"(p));
    return a;
}

#define CP_ASYNC16(dst, src)                                               \
    asm volatile("cp.async.cg.shared.global [%0], [%1], 16;"               \
                 :: "r"(dst), "l"(src) : "memory")
#define CP_COMMIT() asm volatile("cp.async.commit_group;" ::: "memory")
#define CP_WAIT1()  asm volatile("cp.async.wait_group 1;" ::: "memory")

#define LDSM_X4(r0, r1, r2, r3, addr)                                      \
    asm volatile("ldmatrix.sync.aligned.m8n8.x4.shared.b16 "               \
                 "{%0,%1,%2,%3}, [%4];"                                    \
                 : "=r"(r0), "=r"(r1), "=r"(r2), "=r"(r3) : "r"(addr))

#define IMMA16832(c, a0, a1, a2, a3, b0, b1)                               \
    asm volatile("mma.sync.aligned.m16n8k32.row.col.s32.s8.s8.s32 "        \
                 "{%0,%1,%2,%3}, {%4,%5,%6,%7}, {%8,%9}, {%0,%1,%2,%3};"   \
                 : "+r"((c)[0]), "+r"((c)[1]), "+r"((c)[2]), "+r"((c)[3])  \
                 : "r"(a0), "r"(a1), "r"(a2), "r"(a3), "r"(b0), "r"(b1))

__device__ __forceinline__ uint32_t setgt(float v) {
    uint32_t s;
    asm("set.gt.u32.f32 %0, %1, %2;" : "=r"(s) : "f"(v), "f"(MASK_SCORE_THRESH));
    return s;
}

// ---------------------------------------------------------------------------
// One 32x32 tile job (trow,tcol), ksteps [s_lo,s_hi). diag skips the 2
// below-diagonal micro-tiles.
// ---------------------------------------------------------------------------
__device__ __forceinline__ void mma_job(int acc[2][4][4], uint32_t tbase,
                                        int trow, int tcol, int s_lo, int s_hi,
                                        bool diag, uint32_t lrow, uint32_t lhalf) {
    const uint32_t abase = tbase + (uint32_t)(trow * 32 + (int)lrow) * TPITCH;
    const uint32_t bbase = tbase + (uint32_t)(tcol * 32 + (int)lrow) * TPITCH;
    for (int s = s_lo; s < s_hi; s++) {
        const uint32_t kb = (uint32_t)(32 * s) + lhalf;
        uint32_t a0, a1, a2, a3, a4, a5, a6, a7;
        LDSM_X4(a0, a1, a2, a3, abase + kb);
        LDSM_X4(a4, a5, a6, a7, abase + 16u * TPITCH + kb);
        uint32_t b0, b1, b2, b3, b4, b5, b6, b7;
        LDSM_X4(b0, b1, b2, b3, bbase + kb);
        LDSM_X4(b4, b5, b6, b7, bbase + 16u * TPITCH + kb);

        IMMA16832(acc[0][0], a0, a1, a2, a3, b0, b2);
        IMMA16832(acc[0][1], a0, a1, a2, a3, b1, b3);
        IMMA16832(acc[0][2], a0, a1, a2, a3, b4, b6);
        IMMA16832(acc[0][3], a0, a1, a2, a3, b5, b7);
        if (!diag) {
            IMMA16832(acc[1][0], a4, a5, a6, a7, b0, b2);
            IMMA16832(acc[1][1], a4, a5, a6, a7, b1, b3);
        }
        IMMA16832(acc[1][2], a4, a5, a6, a7, b4, b6);
        IMMA16832(acc[1][3], a4, a5, a6, a7, b5, b7);
    }
}

__device__ __forceinline__ void store_job(int acc[2][4][4], int trow, int tcol,
                                          bool diag, int l) {
    const int g4 = l >> 2;
    const int i2 = (l & 3) * 2;
#pragma unroll
    for (int mi = 0; mi < 2; mi++) {
#pragma unroll
        for (int g = 0; g < 4; g++) {
            if (diag && mi == 1 && g < 2) continue;
            int row = trow * 32 + 16 * mi + g4;
            int col = tcol * 32 + 8 * g + i2;
            atomicAdd(&d_igram[row * NDET + col],           acc[mi][g][0]);
            atomicAdd(&d_igram[row * NDET + col + 1],       acc[mi][g][1]);
            atomicAdd(&d_igram[(row + 8) * NDET + col],     acc[mi][g][2]);
            atomicAdd(&d_igram[(row + 8) * NDET + col + 1], acc[mi][g][3]);
        }
    }
}

// ---------------------------------------------------------------------------
// Single fused kernel, 1024 threads (32 warps -> occ 50%, 8 warps/SMSP):
//  Phase 1 (all 148 CTAs): warp-specialized binarize + upper-tri Gram,
//  single __syncthreads per chunk.
//    warps 0-15 (producers): each owns 8 mask rows; cp.async fp32 stage
//      (2-deep) -> binarize -> s8 tile[b] (double buffered)
//    warps 16-31 (consumers): one 32x32-tile job per warp (4 diag full-K +
//      6 off-diag x 2 K-halves = 16 jobs, upper triangle exactly once)
//  Phase 2 (last CTA): O(N^2) NMS / visibility finish + scratch re-zero.
// ---------------------------------------------------------------------------
__global__ void __launch_bounds__(NTHREADS, 1)
postfilter_kernel(const float* __restrict__ masks,
                  const float* __restrict__ boxes,
                  const float* __restrict__ scores,
                  const int*   __restrict__ labels,
                  float*       __restrict__ out) {
    extern __shared__ __align__(16) char smem[];
    char* tiles = smem + NSTAGE * STAGE_BYTES;

    const int tid = threadIdx.x;
    const int w   = tid >> 5;
    const int l   = tid & 31;
    const int k0  = blockIdx.x;

    if (w < 16) {
        // ================= PRODUCER (warps 0-15) =================
        const int p = w;                       // rows 8p..8p+7
        const char* gbase = (const char*)masks +
                            (size_t)(8 * p) * HWPIX * 4 + (size_t)(16 * l);
        const uint32_t smem_base = smem_u32(smem);
        const uint32_t srow = (uint32_t)(8 * p) * 512u + (uint32_t)(16 * l);

        // prologue: fill both stages
#pragma unroll
        for (int s = 0; s < NSTAGE; s++) {
            int kk = k0 + s * GRID;
            if (kk < NCHUNK) {
                const char* g = gbase + (size_t)kk * 512;
                uint32_t d = smem_base + (uint32_t)s * STAGE_BYTES + srow;
#pragma unroll
                for (int r = 0; r < 8; r++)
                    CP_ASYNC16(d + (uint32_t)r * 512u, g + (size_t)r * HWPIX * 4);
            }
            CP_COMMIT();
        }

        int b = 0;
        for (int k = k0; k < NCHUNK; k += GRID, b ^= 1) {
            CP_WAIT1();              // stage[b] complete (this thread's bytes)

            // binarize stage[b] -> tile[b] (consumers are on tile[b^1])
            const float4* st = (const float4*)(smem + b * STAGE_BYTES);
            char* tb = tiles + b * TILE_BYTES;
#pragma unroll
            for (int r = 0; r < 8; r++) {
                float4 v = st[(8 * p + r) * 32 + l];
                uint32_t s0 = setgt(v.x), s1 = setgt(v.y);
                uint32_t s2 = setgt(v.z), s3 = setgt(v.w);
                uint32_t t0 = __byte_perm(s0, s1, 0x0040);
                uint32_t t1 = __byte_perm(s2, s3, 0x0040);
                uint32_t pk = __byte_perm(t0, t1, 0x5410) & 0x01010101u;
                *(uint32_t*)(tb + (uint32_t)(8 * p + r) * TPITCH + 4u * l) = pk;
            }

            __syncthreads();         // R(k): tile[b] published, STS drained

            // refill stage[b] with chunk k + 2*GRID (covered by MMA(k))
            int kn = k + NSTAGE * GRID;
            if (kn < NCHUNK) {
                const char* g = gbase + (size_t)kn * 512;
                uint32_t d = smem_base + (uint32_t)b * STAGE_BYTES + srow;
#pragma unroll
                for (int r = 0; r < 8; r++)
                    CP_ASYNC16(d + (uint32_t)r * 512u, g + (size_t)r * HWPIX * 4);
            }
            CP_COMMIT();
        }
    } else {
        // ================= CONSUMER (warps 16-31) =================
        const int cw = w - 16;
        const uint32_t lrow  = (uint32_t)(l & 15);
        const uint32_t lhalf = (uint32_t)((l >> 4) * 16);

        // 16 jobs: cw 0-3 diag tiles full K; cw 4-15 off-diag K-halves
        static const int OR6[6] = {0, 0, 0, 1, 1, 2};
        static const int OC6[6] = {1, 2, 3, 2, 3, 3};
        int trow, tcol, s_lo, s_hi;
        bool diag;
        if (cw < 4) {
            trow = cw; tcol = cw; s_lo = 0; s_hi = 4; diag = true;
        } else {
            int pr = (cw - 4) >> 1;
            trow = OR6[pr]; tcol = OC6[pr];
            s_lo = ((cw - 4) & 1) * 2; s_hi = s_lo + 2; diag = false;
        }

        int acc[2][4][4];
#pragma unroll
        for (int mi = 0; mi < 2; mi++)
#pragma unroll
            for (int g = 0; g < 4; g++)
#pragma unroll
                for (int e = 0; e < 4; e++) acc[mi][g][e] = 0;

        int b = 0;
        for (int k = k0; k < NCHUNK; k += GRID, b ^= 1) {
            __syncthreads();         // R(k): tile[b] ready
            const uint32_t tbase = smem_u32(tiles + b * TILE_BYTES);
            mma_job(acc, tbase, trow, tcol, s_lo, s_hi, diag, lrow, lhalf);
        }

        store_job(acc, trow, tcol, diag, l);
    }

    // ===================== last-CTA finish phase =====================
    __shared__ int s_rank;
    __syncthreads();
    if (tid == 0) {
        __threadfence();
        s_rank = atomicAdd(&d_done, 1);
    }
    __syncthreads();
    if (s_rank != GRID - 1) return;

    // --- O(N^2) finish, run by the last CTA (1024 threads; j-work tid<128)
    __shared__ float areas[NDET], ssc[NDET];
    __shared__ float x1s[NDET], y1s[NDET], x2s[NDET], y2s[NDET], bareas[NDET];
    __shared__ unsigned char confl[NDET * NDET];
    __shared__ int  ord[NDET];
    __shared__ unsigned char ks[NDET];
    __shared__ unsigned char keepO[NDET];

    const int j = tid;   // valid for tid < 128

    if (j < NDET) {
        areas[j] = (float)__ldcg(&d_igram[j * NDET + j]);
        ssc[j]   = scores[j];
        x1s[j] = boxes[j * 4 + 0];
        y1s[j] = boxes[j * 4 + 1];
        x2s[j] = boxes[j * 4 + 2];
        y2s[j] = boxes[j * 4 + 3];
    }
    __syncthreads();

    // conflict matrix: 1024 threads, thread t -> row jj = t&127, i-slice t>>7
    {
        int jj = tid & 127;
        int i0 = (tid >> 7) * 16;
        float aj = areas[jj];
        for (int i = i0; i < i0 + 16; i++) {
            int lo = (i < jj) ? i : jj;
            int hi = (i < jj) ? jj : i;
            float inter = (float)__ldcg(&d_igram[lo * NDET + hi]);
            float ai    = areas[i];
            float amin  = fminf(ai, aj), amax = fmaxf(ai, aj);
            float iomin = inter / fmaxf(amin, 1.0f);
            float iomax = inter / fmaxf(amax, 1.0f);
            confl[jj * NDET + i] =
                ((iomin > IOMIN_THRESH) || (iomax > IOMAX_THRESH)) ? 1 : 0;
        }
    }
    __syncthreads();

    // re-zero scratch for the next replay (no more d_igram reads below)
    {
#pragma unroll
        for (int i = 0; i < GRAMN / NTHREADS; i++)
            d_igram[tid + NTHREADS * i] = 0;
        if (tid == 0) d_done = 0;
    }

    // stable descending rank
    if (j < NDET) {
        const float sj = ssc[j];
        int r = 0;
        for (int i = 0; i < NDET; i++) {
            float si = ssc[i];
            r += (si > sj) || (si == sj && i < j);
        }
        ord[r] = j;
        ks[r]  = (areas[j] > MIN_MASK_PIXELS) ? 1 : 0;
    }
    __syncthreads();

    // greedy suppression (serial over i, parallel over j; all threads sync)
    for (int i = 0; i < NDET; i++) {
        if (j < NDET && j > i) {
            if (ks[i] && confl[ord[i] * NDET + ord[j]]) ks[j] = 0;
        }
        __syncthreads();
    }

    if (j < NDET) keepO[ord[j]] = ks[j];
    __syncthreads();
    if (j < NDET) {
        unsigned char kj = (keepO[j] && (labels[j] == PED_LABEL)) ? 1 : 0;
        __syncwarp();
        keepO[j] = kj;
        float wbx = x2s[j] - x1s[j], hbx = y2s[j] - y1s[j];
        bareas[j] = fmaxf(wbx * hbx, 1e-6f);
    }
    __syncthreads();

    if (j < NDET) {
        const float sj = ssc[j];
        const bool high_j = (sj >= HIGH_SCORE_THRESH);
        float cover = 0.0f;
        const float bj = bareas[j];
        for (int i = 0; i < NDET; i++) {
            bool occ = (ssc[i] >= HIGH_SCORE_THRESH) && keepO[i] && (i != j);
            if (occ) {
                float ix1 = fmaxf(x1s[i], x1s[j]);
                float iy1 = fmaxf(y1s[i], y1s[j]);
                float ix2 = fminf(x2s[i], x2s[j]);
                float iy2 = fminf(y2s[i], y2s[j]);
                float bi  = fmaxf(ix2 - ix1, 0.0f) * fmaxf(iy2 - iy1, 0.0f);
                cover = fmaxf(cover, bi / bj);
            }
        }
        float vis = 1.0f - cover;
        bool finalk = keepO[j] && (high_j || (vis < VIS_THRESH));
        out[j] = sj * (finalk ? 1.0f : 0.0f);
    }
}

// ---------------------------------------------------------------------------
// kernel_launch — inputs: boxes f32[128,4], scores f32[128], labels i32[128],
// masks f32[128,1,608,1088]; output f32[128].
// ---------------------------------------------------------------------------
extern "C" void kernel_launch(void* const* d_in, const int* in_sizes, int n_in,
                              void* d_out, int out_size) {
    const float* boxes  = (const float*)d_in[0];
    const float* scores = (const float*)d_in[1];
    const int*   labels = (const int*)d_in[2];
    const float* masks  = (const float*)d_in[3];
    float* out = (float*)d_out;

    static bool attr_set = false;
    if (!attr_set) {
        cudaFuncSetAttribute(postfilter_kernel,
                             cudaFuncAttributeMaxDynamicSharedMemorySize,
                             SMEM_DYN);
        attr_set = true;
    }

    postfilter_kernel<<<GRID, NTHREADS, SMEM_DYN>>>(masks, boxes, scores, labels, out);
}